// round 9
// baseline (speedup 1.0000x reference)
#include <cuda_runtime.h>
#include <cstdint>
#include <cstddef>

#define Bsz 128
#define Ssz 1024
#define Dsz 256
#define Hsz 256
#define G3  768

// 402 MB scratch for precomputed input gates gx = x @ W_ih + b_ih
__device__ float g_gx[(size_t)Bsz * Ssz * G3];

typedef unsigned long long ull;

__device__ __forceinline__ ull pack2(float a) {
    ull r;
    asm("mov.b64 %0, {%1, %1};" : "=l"(r) : "f"(a));
    return r;
}
__device__ __forceinline__ ull pk(float a, float b) {
    ull r;
    asm("mov.b64 %0, {%1, %2};" : "=l"(r) : "f"(a), "f"(b));
    return r;
}
__device__ __forceinline__ void fma2(ull& acc, ull a, ull b) {
    asm("fma.rn.f32x2 %0, %1, %2, %0;" : "+l"(acc) : "l"(a), "l"(b));
}
__device__ __forceinline__ float2 unpack2(ull v) {
    float2 f;
    asm("mov.b64 {%0, %1}, %2;" : "=f"(f.x), "=f"(f.y) : "l"(v));
    return f;
}

// ---------------------------------------------------------------------------
// Kernel A: gx[M=131072, 768] = X[M,256] @ W_ih[256,768] + b_ih
// 128x128 block tile, BK=32, double-buffered smem, PACK-FREE inner loop:
// A-tile stored duplicated (a,a) as ull so microtile is pure LDS+FFMA2.
// Per buffer: As2 32KB (ull[32][128]) + Bs 16KB (float[32][128]) = 48KB.
// 2 buffers = 96KB dynamic smem; 2 CTAs/SM.
// ---------------------------------------------------------------------------
#define ABUF_BYTES 49152
#define SMEM_A_BYTES (2 * ABUF_BYTES)

__global__ __launch_bounds__(256, 2) void gemm_gx_kernel(
    const float* __restrict__ X, const float* __restrict__ W,
    const float* __restrict__ bias)
{
    extern __shared__ char smAc[];

    const int tid  = threadIdx.x;
    const int brow = blockIdx.y * 128;
    const int bcol = blockIdx.x * 128;
    const int ty   = tid >> 4;
    const int tx   = tid & 15;

    ull acc2[8][4];
#pragma unroll
    for (int i = 0; i < 8; i++)
#pragma unroll
        for (int j = 0; j < 4; j++) acc2[i][j] = 0ull;

    int aoff[4], akk[4], bkk[4], bcc[4];
#pragma unroll
    for (int it = 0; it < 4; it++) {
        int id = tid + it * 256;
        aoff[it] = id >> 3;            // A row 0..127
        akk[it]  = (id & 7) << 2;      // A k sub 0..28
        bkk[it]  = id >> 5;            // B k 0..31
        bcc[it]  = (id & 31) << 2;     // B col 0..124
    }

    float4 pa[4], pb[4];
#pragma unroll
    for (int it = 0; it < 4; it++) {
        pa[it] = *reinterpret_cast<const float4*>(
            &X[(size_t)(brow + aoff[it]) * Dsz + akk[it]]);
        pb[it] = *reinterpret_cast<const float4*>(
            &W[(size_t)bkk[it] * G3 + bcol + bcc[it]]);
    }

    // commit tile 0 into buffer 0 (A duplicated as ull pairs)
    {
        ull*   As2 = reinterpret_cast<ull*>(smAc);
        float* Bs  = reinterpret_cast<float*>(smAc + 32768);
#pragma unroll
        for (int it = 0; it < 4; it++) {
            As2[(akk[it] + 0) * 128 + aoff[it]] = pack2(pa[it].x);
            As2[(akk[it] + 1) * 128 + aoff[it]] = pack2(pa[it].y);
            As2[(akk[it] + 2) * 128 + aoff[it]] = pack2(pa[it].z);
            As2[(akk[it] + 3) * 128 + aoff[it]] = pack2(pa[it].w);
            *reinterpret_cast<float4*>(&Bs[bkk[it] * 128 + bcc[it]]) = pb[it];
        }
    }
    __syncthreads();

    for (int it8 = 0; it8 < 8; it8++) {
        const int p = it8 & 1;
        ull*   As2 = reinterpret_cast<ull*>(smAc + p * ABUF_BYTES);
        float* Bs  = reinterpret_cast<float*>(smAc + p * ABUF_BYTES + 32768);

        // issue next tile's global loads (hidden under compute below)
        if (it8 < 7) {
            int k0n = (it8 + 1) * 32;
#pragma unroll
            for (int it = 0; it < 4; it++) {
                pa[it] = *reinterpret_cast<const float4*>(
                    &X[(size_t)(brow + aoff[it]) * Dsz + k0n + akk[it]]);
                pb[it] = *reinterpret_cast<const float4*>(
                    &W[(size_t)(k0n + bkk[it]) * G3 + bcol + bcc[it]]);
            }
        }

#pragma unroll 8
        for (int kk = 0; kk < 32; kk++) {
            ull rb2[4];
            ulonglong2 b01 = *reinterpret_cast<ulonglong2*>(&Bs[kk * 128 + tx * 8]);
            ulonglong2 b23 = *reinterpret_cast<ulonglong2*>(&Bs[kk * 128 + tx * 8 + 4]);
            rb2[0] = b01.x; rb2[1] = b01.y; rb2[2] = b23.x; rb2[3] = b23.y;
            const ull* arow = As2 + kk * 128 + ty * 8;
#pragma unroll
            for (int half = 0; half < 2; half++) {
                ulonglong2 l0 = *reinterpret_cast<const ulonglong2*>(arow + half * 4);
                ulonglong2 l1 = *reinterpret_cast<const ulonglong2*>(arow + half * 4 + 2);
                ull a0 = l0.x, a1 = l0.y, a2 = l1.x, a3 = l1.y;
#pragma unroll
                for (int j = 0; j < 4; j++) {
                    fma2(acc2[half * 4 + 0][j], a0, rb2[j]);
                    fma2(acc2[half * 4 + 1][j], a1, rb2[j]);
                    fma2(acc2[half * 4 + 2][j], a2, rb2[j]);
                    fma2(acc2[half * 4 + 3][j], a3, rb2[j]);
                }
            }
        }

        // commit prefetched tile into the OTHER buffer, then single sync
        if (it8 < 7) {
            ull*   As2n = reinterpret_cast<ull*>(smAc + (p ^ 1) * ABUF_BYTES);
            float* Bsn  = reinterpret_cast<float*>(smAc + (p ^ 1) * ABUF_BYTES + 32768);
#pragma unroll
            for (int it = 0; it < 4; it++) {
                As2n[(akk[it] + 0) * 128 + aoff[it]] = pack2(pa[it].x);
                As2n[(akk[it] + 1) * 128 + aoff[it]] = pack2(pa[it].y);
                As2n[(akk[it] + 2) * 128 + aoff[it]] = pack2(pa[it].z);
                As2n[(akk[it] + 3) * 128 + aoff[it]] = pack2(pa[it].w);
                *reinterpret_cast<float4*>(&Bsn[bkk[it] * 128 + bcc[it]]) = pb[it];
            }
            __syncthreads();
        }
    }

#pragma unroll
    for (int i = 0; i < 8; i++) {
        int row = brow + ty * 8 + i;
#pragma unroll
        for (int j2 = 0; j2 < 2; j2++) {
            int col = bcol + tx * 8 + j2 * 4;
            float4 bv = *reinterpret_cast<const float4*>(&bias[col]);
            float2 c0 = unpack2(acc2[i][j2 * 2 + 0]);
            float2 c1 = unpack2(acc2[i][j2 * 2 + 1]);
            float4 cv;
            cv.x = c0.x + bv.x;
            cv.y = c0.y + bv.y;
            cv.z = c1.x + bv.z;
            cv.w = c1.y + bv.w;
            *reinterpret_cast<float4*>(&g_gx[(size_t)row * G3 + col]) = cv;
        }
    }
}

// ---------------------------------------------------------------------------
// Kernel B: persistent GRU recurrence — bulk DSMEM h exchange (R7/R8 WIN
// protocol, NKREG 20) + one-step-ahead gx/mask prefetch.
// ---------------------------------------------------------------------------
#define TPB_B 256
#define NKREG 20
#define NKSM  12

// smem in ull units:
// Ws2[8][12][3][32] | hb2[2][256][4] | red[8][4][3][32] | stage[2][256]
#define ULL_W     0
#define ULL_H     (8 * NKSM * 3 * 32)          // 9216
#define ULL_RED   (ULL_H + 2 * 256 * 4)        // 11264
#define ULL_STAGE (ULL_RED + 8 * 4 * 3 * 32)   // 14336
#define ULL_TOT   (ULL_STAGE + 2 * 256)        // 14848
#define SMEM_B_BYTES (ULL_TOT * 8 + 16)

__device__ __forceinline__ float sigmoidf_fast(float x) {
    return __fdividef(1.0f, 1.0f + __expf(-x));
}
__device__ __forceinline__ float tanhf_fast(float x) {
    x = fminf(fmaxf(x, -15.f), 15.f);
    float e = __expf(2.f * x);
    return __fdividef(e - 1.f, e + 1.f);
}

__device__ __forceinline__ void mbar_wait_parity(uint32_t mbar, uint32_t parity) {
    asm volatile(
        "{\n\t"
        ".reg .pred P;\n\t"
        "WAIT_%=:\n\t"
        "mbarrier.try_wait.parity.acquire.cluster.shared::cta.b64 P, [%0], %1, 0x989680;\n\t"
        "@P bra DONE_%=;\n\t"
        "bra WAIT_%=;\n\t"
        "DONE_%=:\n\t"
        "}"
        :: "r"(mbar), "r"(parity) : "memory");
}

__global__ void __cluster_dims__(4, 1, 1) __launch_bounds__(TPB_B, 1)
gru_rec_kernel(const float* __restrict__ mask,
               const float* __restrict__ Whh,
               const float* __restrict__ bhh,
               float* __restrict__ out)
{
    extern __shared__ ull smu[];
    ull* Ws2   = smu + ULL_W;     // [kq][kk2][g][jp]
    ull* hb2   = smu + ULL_H;     // [2][256 k][4 b] duplicated (h,h)
    ull* red   = smu + ULL_RED;   // [kq][b][g][jp]
    ull* stage = smu + ULL_STAGE; // [2][64 j][4 b] local h staging

    const int tid = threadIdx.x;
    uint32_t rank;
    asm("mov.u32 %0, %%cluster_ctarank;" : "=r"(rank));
    const int ci = (int)blockIdx.x >> 2;

    uint32_t sm_u32;
    asm("{ .reg .u64 t; cvta.to.shared.u64 t, %1; cvt.u32.u64 %0, t; }"
        : "=r"(sm_u32) : "l"(smu));
    const uint32_t hb_u32    = sm_u32 + ULL_H * 8;
    const uint32_t stage_u32 = sm_u32 + ULL_STAGE * 8;
    const uint32_t mbar_u32  = sm_u32 + ULL_TOT * 8;

    // tx-counted mbarriers: 1 arrival (tid0) + 8192B tx (4 x 2KB) per phase
    if (tid == 0) {
        asm volatile("mbarrier.init.shared.b64 [%0], 1;" :: "r"(mbar_u32) : "memory");
        asm volatile("mbarrier.init.shared.b64 [%0], 1;" :: "r"(mbar_u32 + 8) : "memory");
        asm volatile("mbarrier.arrive.expect_tx.shared.b64 _, [%0], 8192;"
                     :: "r"(mbar_u32) : "memory");
        asm volatile("mbarrier.arrive.expect_tx.shared.b64 _, [%0], 8192;"
                     :: "r"(mbar_u32 + 8) : "memory");
    }

    // Stage smem weights: k-offsets NKREG..31 of each 32-k chunk
    for (int idx = tid; idx < 8 * NKSM * 3 * 32; idx += TPB_B) {
        int jp_ = idx & 31;
        int g   = (idx >> 5) % 3;
        int kk  = (idx / 96) % NKSM;
        int kq_ = idx / (96 * NKSM);
        int k   = kq_ * 32 + NKREG + kk;
        int base = k * G3 + g * 256 + (int)rank * 64 + jp_ * 2;
        Ws2[idx] = pk(Whh[base], Whh[base + 1]);
    }
    for (int idx = tid; idx < 2 * 256 * 4; idx += TPB_B) hb2[idx] = 0ull;

    const int kq = tid >> 5;
    const int jp = tid & 31;
    const int k0 = kq * 32;
    const int jg0 = (int)rank * 64 + jp * 2;

    // Register weights: k-offsets 0..NKREG-1, pairs of distinct scalars
    ull wr[NKREG], wz[NKREG], wn[NKREG];
#pragma unroll
    for (int kk = 0; kk < NKREG; kk++) {
        int k = k0 + kk;
        wr[kk] = pk(Whh[k * G3 + jg0],       Whh[k * G3 + jg0 + 1]);
        wz[kk] = pk(Whh[k * G3 + 256 + jg0], Whh[k * G3 + 256 + jg0 + 1]);
        wn[kk] = pk(Whh[k * G3 + 512 + jg0], Whh[k * G3 + 512 + jg0 + 1]);
    }

    // Elementwise mapping: ALL 256 threads: j = tid&63, b = tid>>6
    const int je = tid & 63;
    const int be = tid >> 6;
    const int jge = (int)rank * 64 + je;
    const float bhr = bhh[jge];
    const float bhz = bhh[256 + jge];
    const float bhn = bhh[512 + jge];
    const int bbg = ci * 4 + be;
    const float* gx_p = g_gx + (size_t)bbg * Ssz * G3;
    const float* m_p  = mask + (size_t)bbg * Ssz;
    float* out_p = out + (size_t)bbg * Ssz * Hsz + jge;

    __syncthreads();
    asm volatile("barrier.cluster.arrive.aligned;" ::: "memory");
    asm volatile("barrier.cluster.wait.aligned;" ::: "memory");

    int ph0 = 0, ph1 = 0;

    // preload gx/mask for t = 0
    float gxr = __ldcs(gx_p + jge);
    float gxz = __ldcs(gx_p + 256 + jge);
    float gxn = __ldcs(gx_p + 512 + jge);
    float mt  = __ldg(m_p);

    for (int t = 0; t < Ssz; t++) {
        // issue gx/mask loads for t+1 (consumed a full step later)
        float gxr_n = 0.f, gxz_n = 0.f, gxn_n = 0.f, mt_n = 0.f;
        if (t + 1 < Ssz) {
            const float* gxt1 = gx_p + (size_t)(t + 1) * G3;
            gxr_n = __ldcs(gxt1 + jge);
            gxz_n = __ldcs(gxt1 + 256 + jge);
            gxn_n = __ldcs(gxt1 + 512 + jge);
            mt_n  = __ldg(m_p + t + 1);
        }

        const int mi = t & 1;
        if (t > 0) {
            uint32_t mb = mbar_u32 + (uint32_t)(mi * 8);
            if (mi == 0) { mbar_wait_parity(mb, ph0); ph0 ^= 1; }
            else         { mbar_wait_parity(mb, ph1); ph1 ^= 1; }
            if (tid == 0 && t + 2 < Ssz)
                asm volatile("mbarrier.arrive.expect_tx.shared.b64 _, [%0], 8192;"
                             :: "r"(mb) : "memory");
        }

        float hold = reinterpret_cast<const float*>(
            &hb2[mi * 1024 + jge * 4 + be])[0];

        // ---- gh partial GEMM: k in [k0, k0+32), pack-free FFMA2 ----
        ull ar[4] = {0, 0, 0, 0}, az[4] = {0, 0, 0, 0}, an[4] = {0, 0, 0, 0};
        const ull* hK = hb2 + mi * 1024 + k0 * 4;

#pragma unroll
        for (int kk = 0; kk < NKREG; kk++) {
            ulonglong2 h01 = *reinterpret_cast<const ulonglong2*>(hK + kk * 4);
            ulonglong2 h23 = *reinterpret_cast<const ulonglong2*>(hK + kk * 4 + 2);
            ull hh[4] = {h01.x, h01.y, h23.x, h23.y};
#pragma unroll
            for (int b = 0; b < 4; b++) {
                fma2(ar[b], hh[b], wr[kk]);
                fma2(az[b], hh[b], wz[kk]);
                fma2(an[b], hh[b], wn[kk]);
            }
        }
#pragma unroll
        for (int kk2 = 0; kk2 < NKSM; kk2++) {
            const ull* wb = Ws2 + ((kq * NKSM + kk2) * 3) * 32 + jp;
            ull w_r = wb[0];
            ull w_z = wb[32];
            ull w_n = wb[64];
            int kk = NKREG + kk2;
            ulonglong2 h01 = *reinterpret_cast<const ulonglong2*>(hK + kk * 4);
            ulonglong2 h23 = *reinterpret_cast<const ulonglong2*>(hK + kk * 4 + 2);
            ull hh[4] = {h01.x, h01.y, h23.x, h23.y};
#pragma unroll
            for (int b = 0; b < 4; b++) {
                fma2(ar[b], hh[b], w_r);
                fma2(az[b], hh[b], w_z);
                fma2(an[b], hh[b], w_n);
            }
        }

        // partials -> red[kq][b][g][jp]
        {
            ull* rb = red + kq * 384 + jp;
#pragma unroll
            for (int b = 0; b < 4; b++) {
                rb[b * 96]      = ar[b];
                rb[b * 96 + 32] = az[b];
                rb[b * 96 + 64] = an[b];
            }
        }
        __syncthreads();

        // ---- elementwise gates + h update (ALL 256 threads) ----
        {
            float ghr = bhr, ghz = bhz, ghn = bhn;
            const float* redf = reinterpret_cast<const float*>(red);
            const int fb = be * 192 + je;   // float idx: kq*768 + b*192 + g*64 + j
#pragma unroll
            for (int q = 0; q < 8; q++) {
                const float* rp = redf + q * 768 + fb;
                ghr += rp[0];
                ghz += rp[64];
                ghn += rp[128];
            }
            float r = sigmoidf_fast(gxr + ghr);
            float z = sigmoidf_fast(gxz + ghz);
            float n = tanhf_fast(fmaf(r, ghn, gxn));
            float hnew = fmaf(z, hold - n, n);           // (1-z)*n + z*hold
            float hout = fmaf(mt, hnew - hold, hold);    // m*hnew + (1-m)*hold
            out_p[(size_t)t * Hsz] = hout;

            // stage h pair locally (double-buffered by step parity)
            stage[(t & 1) * 256 + je * 4 + be] = pk(hout, hout);
        }
        __syncthreads();   // stage + red reads complete

        // ---- bulk DSMEM broadcast: 4 x 2KB copies, tx-credited ----
        if (t < Ssz - 1 && tid < 4) {
            asm volatile("fence.proxy.async.shared::cta;" ::: "memory");
            uint32_t src = stage_u32 + (uint32_t)((t & 1) * 256 * 8);
            uint32_t dst_local = hb_u32 +
                (uint32_t)((((t + 1) & 1) * 1024 + (int)rank * 256) * 8);
            uint32_t mb_local = mbar_u32 + (uint32_t)(((t + 1) & 1) * 8);
            uint32_t dst_r, mb_r;
            asm volatile("mapa.shared::cluster.u32 %0, %1, %2;"
                         : "=r"(dst_r) : "r"(dst_local), "r"(tid));
            asm volatile("mapa.shared::cluster.u32 %0, %1, %2;"
                         : "=r"(mb_r) : "r"(mb_local), "r"(tid));
            asm volatile(
                "cp.async.bulk.shared::cluster.shared::cta."
                "mbarrier::complete_tx::bytes [%0], [%1], %2, [%3];"
                :: "r"(dst_r), "r"(src), "r"(2048), "r"(mb_r) : "memory");
        }

        // rotate prefetched gx/mask
        gxr = gxr_n; gxz = gxz_n; gxn = gxn_n; mt = mt_n;
    }
}

// ---------------------------------------------------------------------------
extern "C" void kernel_launch(void* const* d_in, const int* in_sizes, int n_in,
                              void* d_out, int out_size)
{
    (void)in_sizes; (void)n_in; (void)out_size;
    const float* x    = (const float*)d_in[0];
    const float* mask = (const float*)d_in[1];
    const float* Wih  = (const float*)d_in[2];
    const float* Whh  = (const float*)d_in[3];
    const float* bih  = (const float*)d_in[4];
    const float* bhh  = (const float*)d_in[5];
    float* out = (float*)d_out;

    cudaFuncSetAttribute(gemm_gx_kernel,
                         cudaFuncAttributeMaxDynamicSharedMemorySize,
                         SMEM_A_BYTES);
    cudaFuncSetAttribute(gru_rec_kernel,
                         cudaFuncAttributeMaxDynamicSharedMemorySize,
                         SMEM_B_BYTES);

    dim3 gridA(G3 / 128, (Bsz * Ssz) / 128);
    gemm_gx_kernel<<<gridA, 256, SMEM_A_BYTES>>>(x, Wih, bih);

    gru_rec_kernel<<<Bsz, TPB_B, SMEM_B_BYTES>>>(mask, Whh, bhh, out);
}

// round 10
// speedup vs baseline: 1.0592x; 1.0592x over previous
#include <cuda_runtime.h>
#include <cstdint>
#include <cstddef>

#define Bsz 128
#define Ssz 1024
#define Dsz 256
#define Hsz 256
#define G3  768

// 402 MB scratch for precomputed input gates gx = x @ W_ih + b_ih
__device__ float g_gx[(size_t)Bsz * Ssz * G3];

typedef unsigned long long ull;

__device__ __forceinline__ ull pack2(float a) {
    ull r;
    asm("mov.b64 %0, {%1, %1};" : "=l"(r) : "f"(a));
    return r;
}
__device__ __forceinline__ ull pk(float a, float b) {
    ull r;
    asm("mov.b64 %0, {%1, %2};" : "=l"(r) : "f"(a), "f"(b));
    return r;
}
__device__ __forceinline__ void fma2(ull& acc, ull a, ull b) {
    asm("fma.rn.f32x2 %0, %1, %2, %0;" : "+l"(acc) : "l"(a), "l"(b));
}
__device__ __forceinline__ float2 unpack2(ull v) {
    float2 f;
    asm("mov.b64 {%0, %1}, %2;" : "=f"(f.x), "=f"(f.y) : "l"(v));
    return f;
}

// ---------------------------------------------------------------------------
// Kernel A: gx[M=131072, 768] = X[M,256] @ W_ih[256,768] + b_ih
// R8 version (best measured ~1150us): 128x128 tile, BK=32, double-buffered
// float smem, one sync per K-tile, 8x8 microtile FFMA2, 2 CTAs/SM.
// ---------------------------------------------------------------------------
#define SMEM_A_BYTES (2 * 8192 * 4)

__global__ __launch_bounds__(256, 2) void gemm_gx_kernel(
    const float* __restrict__ X, const float* __restrict__ W,
    const float* __restrict__ bias)
{
    extern __shared__ float smA[];
    // buffer p: As = smA + p*8192 (As[k][row]), Bs = As + 4096 (Bs[k][col])

    const int tid  = threadIdx.x;
    const int brow = blockIdx.y * 128;
    const int bcol = blockIdx.x * 128;
    const int ty   = tid >> 4;
    const int tx   = tid & 15;

    ull acc2[8][4];
#pragma unroll
    for (int i = 0; i < 8; i++)
#pragma unroll
        for (int j = 0; j < 4; j++) acc2[i][j] = 0ull;

    int aoff[4], akk[4], bkk[4], bcc[4];
#pragma unroll
    for (int it = 0; it < 4; it++) {
        int id = tid + it * 256;
        aoff[it] = id >> 3;
        akk[it]  = (id & 7) << 2;
        bkk[it]  = id >> 5;
        bcc[it]  = (id & 31) << 2;
    }

    float4 pa[4], pb[4];
#pragma unroll
    for (int it = 0; it < 4; it++) {
        pa[it] = *reinterpret_cast<const float4*>(
            &X[(size_t)(brow + aoff[it]) * Dsz + akk[it]]);
        pb[it] = *reinterpret_cast<const float4*>(
            &W[(size_t)bkk[it] * G3 + bcol + bcc[it]]);
    }

    // commit tile 0 into buffer 0
    {
        float* As = smA;
        float* Bs = smA + 4096;
#pragma unroll
        for (int it = 0; it < 4; it++) {
            As[(akk[it] + 0) * 128 + aoff[it]] = pa[it].x;
            As[(akk[it] + 1) * 128 + aoff[it]] = pa[it].y;
            As[(akk[it] + 2) * 128 + aoff[it]] = pa[it].z;
            As[(akk[it] + 3) * 128 + aoff[it]] = pa[it].w;
            *reinterpret_cast<float4*>(&Bs[bkk[it] * 128 + bcc[it]]) = pb[it];
        }
    }
    __syncthreads();

    for (int it8 = 0; it8 < 8; it8++) {
        const int p = it8 & 1;
        float* As = smA + p * 8192;
        float* Bs = As + 4096;

        if (it8 < 7) {
            int k0n = (it8 + 1) * 32;
#pragma unroll
            for (int it = 0; it < 4; it++) {
                pa[it] = *reinterpret_cast<const float4*>(
                    &X[(size_t)(brow + aoff[it]) * Dsz + k0n + akk[it]]);
                pb[it] = *reinterpret_cast<const float4*>(
                    &W[(size_t)(k0n + bkk[it]) * G3 + bcol + bcc[it]]);
            }
        }

#pragma unroll 8
        for (int kk = 0; kk < 32; kk++) {
            float ra[8];
            ull   rb2[4];
            *reinterpret_cast<float4*>(&ra[0]) =
                *reinterpret_cast<float4*>(&As[kk * 128 + ty * 8]);
            *reinterpret_cast<float4*>(&ra[4]) =
                *reinterpret_cast<float4*>(&As[kk * 128 + ty * 8 + 4]);
            ulonglong2 b01 = *reinterpret_cast<ulonglong2*>(&Bs[kk * 128 + tx * 8]);
            ulonglong2 b23 = *reinterpret_cast<ulonglong2*>(&Bs[kk * 128 + tx * 8 + 4]);
            rb2[0] = b01.x; rb2[1] = b01.y; rb2[2] = b23.x; rb2[3] = b23.y;
#pragma unroll
            for (int i = 0; i < 8; i++) {
                ull ra2 = pack2(ra[i]);
#pragma unroll
                for (int j = 0; j < 4; j++)
                    fma2(acc2[i][j], ra2, rb2[j]);
            }
        }

        if (it8 < 7) {
            float* Asn = smA + (p ^ 1) * 8192;
            float* Bsn = Asn + 4096;
#pragma unroll
            for (int it = 0; it < 4; it++) {
                Asn[(akk[it] + 0) * 128 + aoff[it]] = pa[it].x;
                Asn[(akk[it] + 1) * 128 + aoff[it]] = pa[it].y;
                Asn[(akk[it] + 2) * 128 + aoff[it]] = pa[it].z;
                Asn[(akk[it] + 3) * 128 + aoff[it]] = pa[it].w;
                *reinterpret_cast<float4*>(&Bsn[bkk[it] * 128 + bcc[it]]) = pb[it];
            }
            __syncthreads();
        }
    }

#pragma unroll
    for (int i = 0; i < 8; i++) {
        int row = brow + ty * 8 + i;
#pragma unroll
        for (int j2 = 0; j2 < 2; j2++) {
            int col = bcol + tx * 8 + j2 * 4;
            float4 bv = *reinterpret_cast<const float4*>(&bias[col]);
            float2 c0 = unpack2(acc2[i][j2 * 2 + 0]);
            float2 c1 = unpack2(acc2[i][j2 * 2 + 1]);
            float4 cv;
            cv.x = c0.x + bv.x;
            cv.y = c0.y + bv.y;
            cv.z = c1.x + bv.z;
            cv.w = c1.y + bv.w;
            *reinterpret_cast<float4*>(&g_gx[(size_t)row * G3 + col]) = cv;
        }
    }
}

// ---------------------------------------------------------------------------
// Kernel B: persistent GRU recurrence — bulk DSMEM protocol (R7/R8 WIN),
// now 512 threads = 16 k-chunks of 16 (4 warps/SMSP for latency hiding).
// No stage buffer: ew writes local hb2 slice directly; 3 remote bulk
// copies per step (expect_tx 6144).
// ---------------------------------------------------------------------------
#define TPB_B 512
#define NKCH  16   // k-chunks (one per warp)
#define KPC   16   // k per chunk
#define NKREG 8    // k-offsets in registers
#define NKSM  8    // k-offsets in smem

// smem in ull units: Ws2[16][8][3][32] | hb2[2][256][4] | red[16][4][3][32]
#define ULL_W   0
#define ULL_H   (NKCH * NKSM * 3 * 32)       // 12288
#define ULL_RED (ULL_H + 2 * 256 * 4)        // 14336
#define ULL_TOT (ULL_RED + NKCH * 4 * 3 * 32) // 20480
#define SMEM_B_BYTES (ULL_TOT * 8 + 16)

__device__ __forceinline__ float sigmoidf_fast(float x) {
    return __fdividef(1.0f, 1.0f + __expf(-x));
}
__device__ __forceinline__ float tanhf_fast(float x) {
    x = fminf(fmaxf(x, -15.f), 15.f);
    float e = __expf(2.f * x);
    return __fdividef(e - 1.f, e + 1.f);
}

__device__ __forceinline__ void mbar_wait_parity(uint32_t mbar, uint32_t parity) {
    asm volatile(
        "{\n\t"
        ".reg .pred P;\n\t"
        "WAIT_%=:\n\t"
        "mbarrier.try_wait.parity.acquire.cluster.shared::cta.b64 P, [%0], %1, 0x989680;\n\t"
        "@P bra DONE_%=;\n\t"
        "bra WAIT_%=;\n\t"
        "DONE_%=:\n\t"
        "}"
        :: "r"(mbar), "r"(parity) : "memory");
}

__global__ void __cluster_dims__(4, 1, 1) __launch_bounds__(TPB_B, 1)
gru_rec_kernel(const float* __restrict__ mask,
               const float* __restrict__ Whh,
               const float* __restrict__ bhh,
               float* __restrict__ out)
{
    extern __shared__ ull smu[];
    ull* Ws2 = smu + ULL_W;    // [kq][kk2][g][jp]
    ull* hb2 = smu + ULL_H;    // [2][256 k][4 b] duplicated (h,h)
    ull* red = smu + ULL_RED;  // [kq][b][g][jp]

    const int tid = threadIdx.x;
    uint32_t rank;
    asm("mov.u32 %0, %%cluster_ctarank;" : "=r"(rank));
    const int ci = (int)blockIdx.x >> 2;

    uint32_t sm_u32;
    asm("{ .reg .u64 t; cvta.to.shared.u64 t, %1; cvt.u32.u64 %0, t; }"
        : "=r"(sm_u32) : "l"(smu));
    const uint32_t hb_u32   = sm_u32 + ULL_H * 8;
    const uint32_t mbar_u32 = sm_u32 + ULL_TOT * 8;

    // tx-counted mbarriers: 1 arrival (tid0) + 6144B tx (3 remote x 2KB)
    if (tid == 0) {
        asm volatile("mbarrier.init.shared.b64 [%0], 1;" :: "r"(mbar_u32) : "memory");
        asm volatile("mbarrier.init.shared.b64 [%0], 1;" :: "r"(mbar_u32 + 8) : "memory");
        asm volatile("mbarrier.arrive.expect_tx.shared.b64 _, [%0], 6144;"
                     :: "r"(mbar_u32) : "memory");
        asm volatile("mbarrier.arrive.expect_tx.shared.b64 _, [%0], 6144;"
                     :: "r"(mbar_u32 + 8) : "memory");
    }

    // Stage smem weights: k-offsets NKREG..15 of each 16-k chunk
    for (int idx = tid; idx < NKCH * NKSM * 3 * 32; idx += TPB_B) {
        int jp_ = idx & 31;
        int g   = (idx >> 5) % 3;
        int kk  = (idx / 96) % NKSM;
        int kq_ = idx / (96 * NKSM);
        int k   = kq_ * KPC + NKREG + kk;
        int base = k * G3 + g * 256 + (int)rank * 64 + jp_ * 2;
        Ws2[idx] = pk(Whh[base], Whh[base + 1]);
    }
    for (int idx = tid; idx < 2 * 256 * 4; idx += TPB_B) hb2[idx] = 0ull;

    const int kq = tid >> 5;          // warp: k-chunk 0..15
    const int jp = tid & 31;          // lane: j-pair
    const int k0 = kq * KPC;
    const int jg0 = (int)rank * 64 + jp * 2;

    // Register weights: k-offsets 0..NKREG-1, pairs of distinct scalars
    ull wr[NKREG], wz[NKREG], wn[NKREG];
#pragma unroll
    for (int kk = 0; kk < NKREG; kk++) {
        int k = k0 + kk;
        wr[kk] = pk(Whh[k * G3 + jg0],       Whh[k * G3 + jg0 + 1]);
        wz[kk] = pk(Whh[k * G3 + 256 + jg0], Whh[k * G3 + 256 + jg0 + 1]);
        wn[kk] = pk(Whh[k * G3 + 512 + jg0], Whh[k * G3 + 512 + jg0 + 1]);
    }

    // Elementwise mapping: tid < 256: j = tid&63, b = tid>>6
    const bool ew = (tid < 256);
    const int je = tid & 63;
    const int be = (tid >> 6) & 3;
    const int jge = (int)rank * 64 + je;
    float bhr = 0.f, bhz = 0.f, bhn = 0.f;
    const float* gx_p = nullptr;
    const float* m_p  = nullptr;
    float* out_p = nullptr;
    if (ew) {
        bhr = bhh[jge];
        bhz = bhh[256 + jge];
        bhn = bhh[512 + jge];
        int bbg = ci * 4 + be;
        gx_p  = g_gx + (size_t)bbg * Ssz * G3;
        m_p   = mask + (size_t)bbg * Ssz;
        out_p = out + (size_t)bbg * Ssz * Hsz + jge;
    }

    __syncthreads();
    asm volatile("barrier.cluster.arrive.aligned;" ::: "memory");
    asm volatile("barrier.cluster.wait.aligned;" ::: "memory");

    int ph0 = 0, ph1 = 0;

    // preload gx/mask for t = 0
    float gxr = 0.f, gxz = 0.f, gxn = 0.f, mt = 0.f;
    if (ew) {
        gxr = __ldcs(gx_p + jge);
        gxz = __ldcs(gx_p + 256 + jge);
        gxn = __ldcs(gx_p + 512 + jge);
        mt  = __ldg(m_p);
    }

    for (int t = 0; t < Ssz; t++) {
        // issue gx/mask loads for t+1 (consumed a full step later)
        float gxr_n = 0.f, gxz_n = 0.f, gxn_n = 0.f, mt_n = 0.f;
        if (ew && t + 1 < Ssz) {
            const float* gxt1 = gx_p + (size_t)(t + 1) * G3;
            gxr_n = __ldcs(gxt1 + jge);
            gxz_n = __ldcs(gxt1 + 256 + jge);
            gxn_n = __ldcs(gxt1 + 512 + jge);
            mt_n  = __ldg(m_p + t + 1);
        }

        const int mi = t & 1;
        if (t > 0) {
            uint32_t mb = mbar_u32 + (uint32_t)(mi * 8);
            if (mi == 0) { mbar_wait_parity(mb, ph0); ph0 ^= 1; }
            else         { mbar_wait_parity(mb, ph1); ph1 ^= 1; }
            if (tid == 0 && t + 2 < Ssz)
                asm volatile("mbarrier.arrive.expect_tx.shared.b64 _, [%0], 6144;"
                             :: "r"(mb) : "memory");
        }

        float hold = 0.f;
        if (ew)
            hold = reinterpret_cast<const float*>(
                &hb2[mi * 1024 + jge * 4 + be])[0];

        // ---- gh partial GEMM: k in [k0, k0+16), pack-free FFMA2 ----
        ull ar[4] = {0, 0, 0, 0}, az[4] = {0, 0, 0, 0}, an[4] = {0, 0, 0, 0};
        const ull* hK = hb2 + mi * 1024 + k0 * 4;

#pragma unroll
        for (int kk = 0; kk < NKREG; kk++) {
            ulonglong2 h01 = *reinterpret_cast<const ulonglong2*>(hK + kk * 4);
            ulonglong2 h23 = *reinterpret_cast<const ulonglong2*>(hK + kk * 4 + 2);
            ull hh[4] = {h01.x, h01.y, h23.x, h23.y};
#pragma unroll
            for (int b = 0; b < 4; b++) {
                fma2(ar[b], hh[b], wr[kk]);
                fma2(az[b], hh[b], wz[kk]);
                fma2(an[b], hh[b], wn[kk]);
            }
        }
#pragma unroll
        for (int kk2 = 0; kk2 < NKSM; kk2++) {
            const ull* wb = Ws2 + ((kq * NKSM + kk2) * 3) * 32 + jp;
            ull w_r = wb[0];
            ull w_z = wb[32];
            ull w_n = wb[64];
            int kk = NKREG + kk2;
            ulonglong2 h01 = *reinterpret_cast<const ulonglong2*>(hK + kk * 4);
            ulonglong2 h23 = *reinterpret_cast<const ulonglong2*>(hK + kk * 4 + 2);
            ull hh[4] = {h01.x, h01.y, h23.x, h23.y};
#pragma unroll
            for (int b = 0; b < 4; b++) {
                fma2(ar[b], hh[b], w_r);
                fma2(az[b], hh[b], w_z);
                fma2(an[b], hh[b], w_n);
            }
        }

        // partials -> red[kq][b][g][jp]
        {
            ull* rb = red + kq * 384 + jp;
#pragma unroll
            for (int b = 0; b < 4; b++) {
                rb[b * 96]      = ar[b];
                rb[b * 96 + 32] = az[b];
                rb[b * 96 + 64] = an[b];
            }
        }
        __syncthreads();

        // ---- elementwise gates + h update (tid < 256) ----
        if (ew) {
            float ghr = bhr, ghz = bhz, ghn = bhn;
            const float* redf = reinterpret_cast<const float*>(red);
            const int fb = be * 192 + je;   // float idx: q*768 + b*192 + g*64 + j
#pragma unroll
            for (int q = 0; q < NKCH; q++) {
                const float* rp = redf + q * 768 + fb;
                ghr += rp[0];
                ghz += rp[64];
                ghn += rp[128];
            }
            float r = sigmoidf_fast(gxr + ghr);
            float z = sigmoidf_fast(gxz + ghz);
            float n = tanhf_fast(fmaf(r, ghn, gxn));
            float hnew = fmaf(z, hold - n, n);           // (1-z)*n + z*hold
            float hout = fmaf(mt, hnew - hold, hold);    // m*hnew + (1-m)*hold
            out_p[(size_t)t * Hsz] = hout;

            // write LOCAL hb2[(t+1)&1] slice directly (no stage buffer)
            if (t < Ssz - 1)
                hb2[((t + 1) & 1) * 1024 + jge * 4 + be] = pk(hout, hout);
        }
        __syncthreads();   // local h writes + red reads complete

        // ---- bulk DSMEM broadcast to 3 REMOTE CTAs, tx-credited ----
        if (t < Ssz - 1 && tid < 3) {
            asm volatile("fence.proxy.async.shared::cta;" ::: "memory");
            int pp = ((int)rank + 1 + tid) & 3;
            uint32_t src = hb_u32 +
                (uint32_t)((((t + 1) & 1) * 1024 + (int)rank * 256) * 8);
            uint32_t mb_local = mbar_u32 + (uint32_t)(((t + 1) & 1) * 8);
            uint32_t dst_r, mb_r;
            asm volatile("mapa.shared::cluster.u32 %0, %1, %2;"
                         : "=r"(dst_r) : "r"(src), "r"(pp));
            asm volatile("mapa.shared::cluster.u32 %0, %1, %2;"
                         : "=r"(mb_r) : "r"(mb_local), "r"(pp));
            asm volatile(
                "cp.async.bulk.shared::cluster.shared::cta."
                "mbarrier::complete_tx::bytes [%0], [%1], %2, [%3];"
                :: "r"(dst_r), "r"(src), "r"(2048), "r"(mb_r) : "memory");
        }

        // rotate prefetched gx/mask
        gxr = gxr_n; gxz = gxz_n; gxn = gxn_n; mt = mt_n;
    }
}

// ---------------------------------------------------------------------------
extern "C" void kernel_launch(void* const* d_in, const int* in_sizes, int n_in,
                              void* d_out, int out_size)
{
    (void)in_sizes; (void)n_in; (void)out_size;
    const float* x    = (const float*)d_in[0];
    const float* mask = (const float*)d_in[1];
    const float* Wih  = (const float*)d_in[2];
    const float* Whh  = (const float*)d_in[3];
    const float* bih  = (const float*)d_in[4];
    const float* bhh  = (const float*)d_in[5];
    float* out = (float*)d_out;

    cudaFuncSetAttribute(gemm_gx_kernel,
                         cudaFuncAttributeMaxDynamicSharedMemorySize,
                         SMEM_A_BYTES);
    cudaFuncSetAttribute(gru_rec_kernel,
                         cudaFuncAttributeMaxDynamicSharedMemorySize,
                         SMEM_B_BYTES);

    dim3 gridA(G3 / 128, (Bsz * Ssz) / 128);
    gemm_gx_kernel<<<gridA, 256, SMEM_A_BYTES>>>(x, Wih, bih);

    gru_rec_kernel<<<Bsz, TPB_B, SMEM_B_BYTES>>>(mask, Whh, bhh, out);
}

// round 12
// speedup vs baseline: 1.4322x; 1.3522x over previous
#include <cuda_runtime.h>
#include <cuda_bf16.h>
#include <cstdint>
#include <cstddef>

#define Bsz 128
#define Ssz 1024
#define Dsz 256
#define Hsz 256
#define G3  768

// Scratch: gx (fp32) + bf16 hi/lo splits of X and W_ih
__device__ float g_gx[(size_t)Bsz * Ssz * G3];
__device__ __nv_bfloat16 g_xhi[(size_t)Bsz * Ssz * Dsz];
__device__ __nv_bfloat16 g_xlo[(size_t)Bsz * Ssz * Dsz];
__device__ __nv_bfloat16 g_whi[Dsz * G3];
__device__ __nv_bfloat16 g_wlo[Dsz * G3];

typedef unsigned long long ull;

__device__ __forceinline__ ull pk(float a, float b) {
    ull r;
    asm("mov.b64 %0, {%1, %2};" : "=l"(r) : "f"(a), "f"(b));
    return r;
}
__device__ __forceinline__ void fma2(ull& acc, ull a, ull b) {
    asm("fma.rn.f32x2 %0, %1, %2, %0;" : "+l"(acc) : "l"(a), "l"(b));
}

// ===========================================================================
// Split kernels: fp32 -> bf16 (hi) + bf16 (residual lo)
// ===========================================================================
__device__ __forceinline__ void split8(const float* src, __nv_bfloat16* dhi,
                                       __nv_bfloat16* dlo, size_t i) {
    float4 v0 = *reinterpret_cast<const float4*>(src + i);
    float4 v1 = *reinterpret_cast<const float4*>(src + i + 4);
    float v[8] = {v0.x, v0.y, v0.z, v0.w, v1.x, v1.y, v1.z, v1.w};
    unsigned h[4], l[4];
#pragma unroll
    for (int e = 0; e < 4; e++) {
        __nv_bfloat16 h0 = __float2bfloat16(v[e * 2]);
        __nv_bfloat16 h1 = __float2bfloat16(v[e * 2 + 1]);
        __nv_bfloat16 l0 = __float2bfloat16(v[e * 2]     - __bfloat162float(h0));
        __nv_bfloat16 l1 = __float2bfloat16(v[e * 2 + 1] - __bfloat162float(h1));
        h[e] = (unsigned)*reinterpret_cast<unsigned short*>(&h0) |
               ((unsigned)*reinterpret_cast<unsigned short*>(&h1) << 16);
        l[e] = (unsigned)*reinterpret_cast<unsigned short*>(&l0) |
               ((unsigned)*reinterpret_cast<unsigned short*>(&l1) << 16);
    }
    *reinterpret_cast<uint4*>(dhi + i) = make_uint4(h[0], h[1], h[2], h[3]);
    *reinterpret_cast<uint4*>(dlo + i) = make_uint4(l[0], l[1], l[2], l[3]);
}

__global__ __launch_bounds__(256) void split_x_kernel(const float* __restrict__ X) {
    size_t i = ((size_t)blockIdx.x * 256 + threadIdx.x) * 8;
    split8(X, g_xhi, g_xlo, i);
}
__global__ __launch_bounds__(256) void split_w_kernel(const float* __restrict__ W) {
    size_t i = ((size_t)blockIdx.x * 256 + threadIdx.x) * 8;
    split8(W, g_whi, g_wlo, i);
}

// ===========================================================================
// Kernel A: gx = X @ W_ih + b_ih via mma.sync bf16 (HMMA), 3-term split as
// K_eff=768 (panels: Xhi*Whi, Xhi*Wlo, Xlo*Whi). CTA 128x128, 8 warps of
// 64x32, K-step 32, double-buffered padded smem, fp32 accum, fused bias.
// ===========================================================================
#define APAD 40    // bf16 per As row (32 + 8 pad)
#define BPAD 136   // bf16 per Bs row (128 + 8 pad)

__global__ __launch_bounds__(256, 2) void gemm_gx_mma(const float* __restrict__ bias)
{
    __shared__ __nv_bfloat16 As[2][128 * APAD];
    __shared__ __nv_bfloat16 Bs[2][32 * BPAD];

    const int tid  = threadIdx.x;
    const int lane = tid & 31;
    const int wid  = tid >> 5;
    const int brow = blockIdx.y * 128;
    const int bcol = blockIdx.x * 128;
    const int warp_m = (wid >> 2) * 64;
    const int warp_n = (wid & 3) * 32;

    float c[4][4][4];
#pragma unroll
    for (int tm = 0; tm < 4; tm++)
#pragma unroll
        for (int tn = 0; tn < 4; tn++)
#pragma unroll
            for (int r = 0; r < 4; r++) c[tm][tn][r] = 0.f;

    // per-thread load coords (2 chunks of 16B each for A and B)
    int arow[2], ak8[2], bkr[2], bn8[2];
#pragma unroll
    for (int ch = 0; ch < 2; ch++) {
        int id = tid + ch * 256;
        arow[ch] = id >> 2;
        ak8[ch]  = (id & 3) * 8;
        bkr[ch]  = id >> 4;
        bn8[ch]  = (id & 15) * 8;
    }

    // smem u32 bases
    uint32_t asB, bsB;
    asm("{ .reg .u64 t; cvta.to.shared.u64 t, %1; cvt.u32.u64 %0, t; }"
        : "=r"(asB) : "l"(&As[0][0]));
    asm("{ .reg .u64 t; cvta.to.shared.u64 t, %1; cvt.u32.u64 %0, t; }"
        : "=r"(bsB) : "l"(&Bs[0][0]));

    // lane-dependent ldmatrix offsets (bytes)
    const uint32_t aLaneOff = (uint32_t)(((lane & 15) * APAD + (lane >> 4) * 8) * 2);
    const uint32_t bLaneOff = (uint32_t)(((((lane >> 3) & 1) * 8 + (lane & 7)) * BPAD
                                          + (lane >> 4) * 8) * 2);

    // prologue: load iteration 0 (panel 0, k0 = 0)
    uint4 ra[2], rb[2];
#pragma unroll
    for (int ch = 0; ch < 2; ch++) {
        ra[ch] = *reinterpret_cast<const uint4*>(
            &g_xhi[(size_t)(brow + arow[ch]) * Dsz + ak8[ch]]);
        rb[ch] = *reinterpret_cast<const uint4*>(
            &g_whi[(size_t)bkr[ch] * G3 + bcol + bn8[ch]]);
    }

#pragma unroll 1
    for (int it = 0; it < 24; it++) {
        const int buf = it & 1;

        // commit staged regs to smem[buf]
#pragma unroll
        for (int ch = 0; ch < 2; ch++) {
            *reinterpret_cast<uint4*>(&As[buf][arow[ch] * APAD + ak8[ch]]) = ra[ch];
            *reinterpret_cast<uint4*>(&Bs[buf][bkr[ch] * BPAD + bn8[ch]]) = rb[ch];
        }
        __syncthreads();

        // issue next iteration's global loads
        if (it + 1 < 24) {
            int p  = (it + 1) >> 3;
            int k0 = ((it + 1) & 7) * 32;
            const __nv_bfloat16* Ag = (p < 2) ? g_xhi : g_xlo;
            const __nv_bfloat16* Bg = (p == 1) ? g_wlo : g_whi;
#pragma unroll
            for (int ch = 0; ch < 2; ch++) {
                ra[ch] = *reinterpret_cast<const uint4*>(
                    &Ag[(size_t)(brow + arow[ch]) * Dsz + k0 + ak8[ch]]);
                rb[ch] = *reinterpret_cast<const uint4*>(
                    &Bg[(size_t)(k0 + bkr[ch]) * G3 + bcol + bn8[ch]]);
            }
        }

        // compute from smem[buf]
        const uint32_t asb = asB + (uint32_t)(buf * 128 * APAD * 2);
        const uint32_t bsb = bsB + (uint32_t)(buf * 32 * BPAD * 2);
#pragma unroll
        for (int kh = 0; kh < 2; kh++) {
            uint32_t a[4][4];
#pragma unroll
            for (int tm = 0; tm < 4; tm++) {
                uint32_t addr = asb + aLaneOff +
                    (uint32_t)(((warp_m + tm * 16) * APAD + kh * 16) * 2);
                asm volatile(
                    "ldmatrix.sync.aligned.m8n8.x4.shared.b16 {%0,%1,%2,%3}, [%4];"
                    : "=r"(a[tm][0]), "=r"(a[tm][1]), "=r"(a[tm][2]), "=r"(a[tm][3])
                    : "r"(addr));
            }
            uint32_t b[4][2];
#pragma unroll
            for (int tnh = 0; tnh < 2; tnh++) {
                uint32_t addr = bsb + bLaneOff +
                    (uint32_t)((kh * 16 * BPAD + warp_n + tnh * 16) * 2);
                uint32_t r0, r1, r2, r3;
                asm volatile(
                    "ldmatrix.sync.aligned.m8n8.x4.trans.shared.b16 {%0,%1,%2,%3}, [%4];"
                    : "=r"(r0), "=r"(r1), "=r"(r2), "=r"(r3)
                    : "r"(addr));
                b[tnh * 2][0] = r0; b[tnh * 2][1] = r1;
                b[tnh * 2 + 1][0] = r2; b[tnh * 2 + 1][1] = r3;
            }
#pragma unroll
            for (int tm = 0; tm < 4; tm++)
#pragma unroll
                for (int tn = 0; tn < 4; tn++) {
                    asm volatile(
                        "mma.sync.aligned.m16n8k16.row.col.f32.bf16.bf16.f32 "
                        "{%0,%1,%2,%3}, {%4,%5,%6,%7}, {%8,%9}, {%0,%1,%2,%3};"
                        : "+f"(c[tm][tn][0]), "+f"(c[tm][tn][1]),
                          "+f"(c[tm][tn][2]), "+f"(c[tm][tn][3])
                        : "r"(a[tm][0]), "r"(a[tm][1]), "r"(a[tm][2]), "r"(a[tm][3]),
                          "r"(b[tn][0]), "r"(b[tn][1]));
                }
        }
    }

    // epilogue: add bias, store fp32 (float2 per fragment half)
#pragma unroll
    for (int tm = 0; tm < 4; tm++) {
        int m0 = brow + warp_m + tm * 16 + (lane >> 2);
#pragma unroll
        for (int tn = 0; tn < 4; tn++) {
            int n0 = bcol + warp_n + tn * 8 + (lane & 3) * 2;
            float2 bv = *reinterpret_cast<const float2*>(&bias[n0]);
            float2 v0 = make_float2(c[tm][tn][0] + bv.x, c[tm][tn][1] + bv.y);
            float2 v1 = make_float2(c[tm][tn][2] + bv.x, c[tm][tn][3] + bv.y);
            *reinterpret_cast<float2*>(&g_gx[(size_t)m0 * G3 + n0]) = v0;
            *reinterpret_cast<float2*>(&g_gx[(size_t)(m0 + 8) * G3 + n0]) = v1;
        }
    }
}

// ===========================================================================
// Kernel B: persistent GRU recurrence — EXACT R8 configuration (1807us):
// bulk DSMEM h exchange, NKREG 20, TPB 256.
// ===========================================================================
#define TPB_B 256
#define NKREG 20
#define NKSM  12

#define ULL_W     0
#define ULL_H     (8 * NKSM * 3 * 32)          // 9216
#define ULL_RED   (ULL_H + 2 * 256 * 4)        // 11264
#define ULL_STAGE (ULL_RED + 8 * 4 * 3 * 32)   // 14336
#define ULL_TOT   (ULL_STAGE + 2 * 256)        // 14848
#define SMEM_B_BYTES (ULL_TOT * 8 + 16)

__device__ __forceinline__ float sigmoidf_fast(float x) {
    return __fdividef(1.0f, 1.0f + __expf(-x));
}
__device__ __forceinline__ float tanhf_fast(float x) {
    x = fminf(fmaxf(x, -15.f), 15.f);
    float e = __expf(2.f * x);
    return __fdividef(e - 1.f, e + 1.f);
}

__device__ __forceinline__ void mbar_wait_parity(uint32_t mbar, uint32_t parity) {
    asm volatile(
        "{\n\t"
        ".reg .pred P;\n\t"
        "WAIT_%=:\n\t"
        "mbarrier.try_wait.parity.acquire.cluster.shared::cta.b64 P, [%0], %1, 0x989680;\n\t"
        "@P bra DONE_%=;\n\t"
        "bra WAIT_%=;\n\t"
        "DONE_%=:\n\t"
        "}"
        :: "r"(mbar), "r"(parity) : "memory");
}

__global__ void __cluster_dims__(4, 1, 1) __launch_bounds__(TPB_B, 1)
gru_rec_kernel(const float* __restrict__ mask,
               const float* __restrict__ Whh,
               const float* __restrict__ bhh,
               float* __restrict__ out)
{
    extern __shared__ ull smu[];
    ull* Ws2   = smu + ULL_W;
    ull* hb2   = smu + ULL_H;
    ull* red   = smu + ULL_RED;
    ull* stage = smu + ULL_STAGE;

    const int tid = threadIdx.x;
    uint32_t rank;
    asm("mov.u32 %0, %%cluster_ctarank;" : "=r"(rank));
    const int ci = (int)blockIdx.x >> 2;

    uint32_t sm_u32;
    asm("{ .reg .u64 t; cvta.to.shared.u64 t, %1; cvt.u32.u64 %0, t; }"
        : "=r"(sm_u32) : "l"(smu));
    const uint32_t hb_u32    = sm_u32 + ULL_H * 8;
    const uint32_t stage_u32 = sm_u32 + ULL_STAGE * 8;
    const uint32_t mbar_u32  = sm_u32 + ULL_TOT * 8;

    if (tid == 0) {
        asm volatile("mbarrier.init.shared.b64 [%0], 1;" :: "r"(mbar_u32) : "memory");
        asm volatile("mbarrier.init.shared.b64 [%0], 1;" :: "r"(mbar_u32 + 8) : "memory");
        asm volatile("mbarrier.arrive.expect_tx.shared.b64 _, [%0], 8192;"
                     :: "r"(mbar_u32) : "memory");
        asm volatile("mbarrier.arrive.expect_tx.shared.b64 _, [%0], 8192;"
                     :: "r"(mbar_u32 + 8) : "memory");
    }

    for (int idx = tid; idx < 8 * NKSM * 3 * 32; idx += TPB_B) {
        int jp_ = idx & 31;
        int g   = (idx >> 5) % 3;
        int kk  = (idx / 96) % NKSM;
        int kq_ = idx / (96 * NKSM);
        int k   = kq_ * 32 + NKREG + kk;
        int base = k * G3 + g * 256 + (int)rank * 64 + jp_ * 2;
        Ws2[idx] = pk(Whh[base], Whh[base + 1]);
    }
    for (int idx = tid; idx < 2 * 256 * 4; idx += TPB_B) hb2[idx] = 0ull;

    const int kq = tid >> 5;
    const int jp = tid & 31;
    const int k0 = kq * 32;
    const int jg0 = (int)rank * 64 + jp * 2;

    ull wr[NKREG], wz[NKREG], wn[NKREG];
#pragma unroll
    for (int kk = 0; kk < NKREG; kk++) {
        int k = k0 + kk;
        wr[kk] = pk(Whh[k * G3 + jg0],       Whh[k * G3 + jg0 + 1]);
        wz[kk] = pk(Whh[k * G3 + 256 + jg0], Whh[k * G3 + 256 + jg0 + 1]);
        wn[kk] = pk(Whh[k * G3 + 512 + jg0], Whh[k * G3 + 512 + jg0 + 1]);
    }

    const int je = tid & 63;
    const int be = tid >> 6;
    const int jge = (int)rank * 64 + je;
    const float bhr = bhh[jge];
    const float bhz = bhh[256 + jge];
    const float bhn = bhh[512 + jge];
    const int bbg = ci * 4 + be;
    const float* gx_p = g_gx + (size_t)bbg * Ssz * G3;
    const float* m_p  = mask + (size_t)bbg * Ssz;
    float* out_p = out + (size_t)bbg * Ssz * Hsz + jge;

    __syncthreads();
    asm volatile("barrier.cluster.arrive.aligned;" ::: "memory");
    asm volatile("barrier.cluster.wait.aligned;" ::: "memory");

    int ph0 = 0, ph1 = 0;

    for (int t = 0; t < Ssz; t++) {
        const float* gxt = gx_p + (size_t)t * G3;
        float gxr = __ldcs(gxt + jge);
        float gxz = __ldcs(gxt + 256 + jge);
        float gxn = __ldcs(gxt + 512 + jge);
        float mt  = __ldg(m_p + t);

        const int mi = t & 1;
        if (t > 0) {
            uint32_t mb = mbar_u32 + (uint32_t)(mi * 8);
            if (mi == 0) { mbar_wait_parity(mb, ph0); ph0 ^= 1; }
            else         { mbar_wait_parity(mb, ph1); ph1 ^= 1; }
            if (tid == 0 && t + 2 < Ssz)
                asm volatile("mbarrier.arrive.expect_tx.shared.b64 _, [%0], 8192;"
                             :: "r"(mb) : "memory");
        }

        float hold = reinterpret_cast<const float*>(
            &hb2[mi * 1024 + jge * 4 + be])[0];

        ull ar[4] = {0, 0, 0, 0}, az[4] = {0, 0, 0, 0}, an[4] = {0, 0, 0, 0};
        const ull* hK = hb2 + mi * 1024 + k0 * 4;

#pragma unroll
        for (int kk = 0; kk < NKREG; kk++) {
            ulonglong2 h01 = *reinterpret_cast<const ulonglong2*>(hK + kk * 4);
            ulonglong2 h23 = *reinterpret_cast<const ulonglong2*>(hK + kk * 4 + 2);
            ull hh[4] = {h01.x, h01.y, h23.x, h23.y};
#pragma unroll
            for (int b = 0; b < 4; b++) {
                fma2(ar[b], hh[b], wr[kk]);
                fma2(az[b], hh[b], wz[kk]);
                fma2(an[b], hh[b], wn[kk]);
            }
        }
#pragma unroll
        for (int kk2 = 0; kk2 < NKSM; kk2++) {
            const ull* wb = Ws2 + ((kq * NKSM + kk2) * 3) * 32 + jp;
            ull w_r = wb[0];
            ull w_z = wb[32];
            ull w_n = wb[64];
            int kk = NKREG + kk2;
            ulonglong2 h01 = *reinterpret_cast<const ulonglong2*>(hK + kk * 4);
            ulonglong2 h23 = *reinterpret_cast<const ulonglong2*>(hK + kk * 4 + 2);
            ull hh[4] = {h01.x, h01.y, h23.x, h23.y};
#pragma unroll
            for (int b = 0; b < 4; b++) {
                fma2(ar[b], hh[b], w_r);
                fma2(az[b], hh[b], w_z);
                fma2(an[b], hh[b], w_n);
            }
        }

        {
            ull* rb = red + kq * 384 + jp;
#pragma unroll
            for (int b = 0; b < 4; b++) {
                rb[b * 96]      = ar[b];
                rb[b * 96 + 32] = az[b];
                rb[b * 96 + 64] = an[b];
            }
        }
        __syncthreads();

        {
            float ghr = bhr, ghz = bhz, ghn = bhn;
            const float* redf = reinterpret_cast<const float*>(red);
            const int fb = be * 192 + je;
#pragma unroll
            for (int q = 0; q < 8; q++) {
                const float* rp = redf + q * 768 + fb;
                ghr += rp[0];
                ghz += rp[64];
                ghn += rp[128];
            }
            float r = sigmoidf_fast(gxr + ghr);
            float z = sigmoidf_fast(gxz + ghz);
            float n = tanhf_fast(fmaf(r, ghn, gxn));
            float hnew = fmaf(z, hold - n, n);
            float hout = fmaf(mt, hnew - hold, hold);
            out_p[(size_t)t * Hsz] = hout;

            stage[(t & 1) * 256 + je * 4 + be] = pk(hout, hout);
        }
        __syncthreads();

        if (t < Ssz - 1 && tid < 4) {
            asm volatile("fence.proxy.async.shared::cta;" ::: "memory");
            uint32_t src = stage_u32 + (uint32_t)((t & 1) * 256 * 8);
            uint32_t dst_local = hb_u32 +
                (uint32_t)((((t + 1) & 1) * 1024 + (int)rank * 256) * 8);
            uint32_t mb_local = mbar_u32 + (uint32_t)(((t + 1) & 1) * 8);
            uint32_t dst_r, mb_r;
            asm volatile("mapa.shared::cluster.u32 %0, %1, %2;"
                         : "=r"(dst_r) : "r"(dst_local), "r"(tid));
            asm volatile("mapa.shared::cluster.u32 %0, %1, %2;"
                         : "=r"(mb_r) : "r"(mb_local), "r"(tid));
            asm volatile(
                "cp.async.bulk.shared::cluster.shared::cta."
                "mbarrier::complete_tx::bytes [%0], [%1], %2, [%3];"
                :: "r"(dst_r), "r"(src), "r"(2048), "r"(mb_r) : "memory");
        }
    }
}

// ---------------------------------------------------------------------------
extern "C" void kernel_launch(void* const* d_in, const int* in_sizes, int n_in,
                              void* d_out, int out_size)
{
    (void)in_sizes; (void)n_in; (void)out_size;
    const float* x    = (const float*)d_in[0];
    const float* mask = (const float*)d_in[1];
    const float* Wih  = (const float*)d_in[2];
    const float* Whh  = (const float*)d_in[3];
    const float* bih  = (const float*)d_in[4];
    const float* bhh  = (const float*)d_in[5];
    float* out = (float*)d_out;

    cudaFuncSetAttribute(gru_rec_kernel,
                         cudaFuncAttributeMaxDynamicSharedMemorySize,
                         SMEM_B_BYTES);

    // 1. split X and W_ih into bf16 hi/lo
    split_x_kernel<<<(Bsz * Ssz * Dsz) / (256 * 8), 256>>>(x);
    split_w_kernel<<<(Dsz * G3) / (256 * 8), 256>>>(Wih);

    // 2. gx GEMM on tensor cores (HMMA via mma.sync)
    dim3 gridA(G3 / 128, (Bsz * Ssz) / 128);   // 6 x 1024
    gemm_gx_mma<<<gridA, 256>>>(bih);

    // 3. recurrence
    gru_rec_kernel<<<Bsz, TPB_B, SMEM_B_BYTES>>>(mask, Whh, bhh, out);
}

// round 13
// speedup vs baseline: 1.4376x; 1.0038x over previous
#include <cuda_runtime.h>
#include <cuda_bf16.h>
#include <cstdint>
#include <cstddef>

#define Bsz 128
#define Ssz 1024
#define Dsz 256
#define Hsz 256
#define G3  768

// Scratch: gx (fp32) + bf16 hi/lo splits of X and W_ih
__device__ float g_gx[(size_t)Bsz * Ssz * G3];
__device__ __nv_bfloat16 g_xhi[(size_t)Bsz * Ssz * Dsz];
__device__ __nv_bfloat16 g_xlo[(size_t)Bsz * Ssz * Dsz];
__device__ __nv_bfloat16 g_whi[Dsz * G3];
__device__ __nv_bfloat16 g_wlo[Dsz * G3];

typedef unsigned long long ull;

__device__ __forceinline__ ull pk(float a, float b) {
    ull r;
    asm("mov.b64 %0, {%1, %2};" : "=l"(r) : "f"(a), "f"(b));
    return r;
}
__device__ __forceinline__ void fma2(ull& acc, ull a, ull b) {
    asm("fma.rn.f32x2 %0, %1, %2, %0;" : "+l"(acc) : "l"(a), "l"(b));
}

// ===========================================================================
// Split kernels: fp32 -> bf16 (hi) + bf16 (residual lo)
// ===========================================================================
__device__ __forceinline__ void split8(const float* src, __nv_bfloat16* dhi,
                                       __nv_bfloat16* dlo, size_t i) {
    float4 v0 = *reinterpret_cast<const float4*>(src + i);
    float4 v1 = *reinterpret_cast<const float4*>(src + i + 4);
    float v[8] = {v0.x, v0.y, v0.z, v0.w, v1.x, v1.y, v1.z, v1.w};
    unsigned h[4], l[4];
#pragma unroll
    for (int e = 0; e < 4; e++) {
        __nv_bfloat16 h0 = __float2bfloat16(v[e * 2]);
        __nv_bfloat16 h1 = __float2bfloat16(v[e * 2 + 1]);
        __nv_bfloat16 l0 = __float2bfloat16(v[e * 2]     - __bfloat162float(h0));
        __nv_bfloat16 l1 = __float2bfloat16(v[e * 2 + 1] - __bfloat162float(h1));
        h[e] = (unsigned)*reinterpret_cast<unsigned short*>(&h0) |
               ((unsigned)*reinterpret_cast<unsigned short*>(&h1) << 16);
        l[e] = (unsigned)*reinterpret_cast<unsigned short*>(&l0) |
               ((unsigned)*reinterpret_cast<unsigned short*>(&l1) << 16);
    }
    *reinterpret_cast<uint4*>(dhi + i) = make_uint4(h[0], h[1], h[2], h[3]);
    *reinterpret_cast<uint4*>(dlo + i) = make_uint4(l[0], l[1], l[2], l[3]);
}

__global__ __launch_bounds__(256) void split_x_kernel(const float* __restrict__ X) {
    size_t i = ((size_t)blockIdx.x * 256 + threadIdx.x) * 8;
    split8(X, g_xhi, g_xlo, i);
}
__global__ __launch_bounds__(256) void split_w_kernel(const float* __restrict__ W) {
    size_t i = ((size_t)blockIdx.x * 256 + threadIdx.x) * 8;
    split8(W, g_whi, g_wlo, i);
}

// ===========================================================================
// Kernel A: gx = X @ W_ih + b_ih via mma.sync bf16 (HMMA), 3-term split as
// K_eff=768. CTA 128x128, 8 warps of 64x32, K-step 32, double-buffered smem,
// fp32 accum. NEW: smem-staged epilogue for fully-coalesced float4 stores.
// ===========================================================================
#define APAD 40    // bf16 per As row (32 + 8 pad)
#define BPAD 136   // bf16 per Bs row (128 + 8 pad)
#define AS_BUF (128 * APAD * 2)          // 10240 B per A buffer
#define BS_BUF (32 * BPAD * 2)           // 8704 B per B buffer
#define BS_BASE (2 * AS_BUF)             // 20480
#define SMEM_GEMM (BS_BASE + 2 * BS_BUF) // 37888 B
#define EPAD 136   // floats per staged row (128 + 8) -> row offset = 8 banks

__global__ __launch_bounds__(256, 2) void gemm_gx_mma(const float* __restrict__ bias)
{
    extern __shared__ char smg[];
    const int tid  = threadIdx.x;
    const int lane = tid & 31;
    const int wid  = tid >> 5;
    const int brow = blockIdx.y * 128;
    const int bcol = blockIdx.x * 128;
    const int warp_m = (wid >> 2) * 64;
    const int warp_n = (wid & 3) * 32;

    float c[4][4][4];
#pragma unroll
    for (int tm = 0; tm < 4; tm++)
#pragma unroll
        for (int tn = 0; tn < 4; tn++)
#pragma unroll
            for (int r = 0; r < 4; r++) c[tm][tn][r] = 0.f;

    int arow[2], ak8[2], bkr[2], bn8[2];
#pragma unroll
    for (int ch = 0; ch < 2; ch++) {
        int id = tid + ch * 256;
        arow[ch] = id >> 2;
        ak8[ch]  = (id & 3) * 8;
        bkr[ch]  = id >> 4;
        bn8[ch]  = (id & 15) * 8;
    }

    uint32_t smB;
    asm("{ .reg .u64 t; cvta.to.shared.u64 t, %1; cvt.u32.u64 %0, t; }"
        : "=r"(smB) : "l"(smg));

    const uint32_t aLaneOff = (uint32_t)(((lane & 15) * APAD + (lane >> 4) * 8) * 2);
    const uint32_t bLaneOff = (uint32_t)(((((lane >> 3) & 1) * 8 + (lane & 7)) * BPAD
                                          + (lane >> 4) * 8) * 2);

    // prologue: load iteration 0 (panel 0, k0 = 0)
    uint4 ra[2], rb[2];
#pragma unroll
    for (int ch = 0; ch < 2; ch++) {
        ra[ch] = *reinterpret_cast<const uint4*>(
            &g_xhi[(size_t)(brow + arow[ch]) * Dsz + ak8[ch]]);
        rb[ch] = *reinterpret_cast<const uint4*>(
            &g_whi[(size_t)bkr[ch] * G3 + bcol + bn8[ch]]);
    }

#pragma unroll 1
    for (int it = 0; it < 24; it++) {
        const int buf = it & 1;
        __nv_bfloat16* As = reinterpret_cast<__nv_bfloat16*>(smg + buf * AS_BUF);
        __nv_bfloat16* Bs = reinterpret_cast<__nv_bfloat16*>(smg + BS_BASE + buf * BS_BUF);

        // commit staged regs to smem[buf]
#pragma unroll
        for (int ch = 0; ch < 2; ch++) {
            *reinterpret_cast<uint4*>(&As[arow[ch] * APAD + ak8[ch]]) = ra[ch];
            *reinterpret_cast<uint4*>(&Bs[bkr[ch] * BPAD + bn8[ch]]) = rb[ch];
        }
        __syncthreads();

        // issue next iteration's global loads
        if (it + 1 < 24) {
            int p  = (it + 1) >> 3;
            int k0 = ((it + 1) & 7) * 32;
            const __nv_bfloat16* Ag = (p < 2) ? g_xhi : g_xlo;
            const __nv_bfloat16* Bg = (p == 1) ? g_wlo : g_whi;
#pragma unroll
            for (int ch = 0; ch < 2; ch++) {
                ra[ch] = *reinterpret_cast<const uint4*>(
                    &Ag[(size_t)(brow + arow[ch]) * Dsz + k0 + ak8[ch]]);
                rb[ch] = *reinterpret_cast<const uint4*>(
                    &Bg[(size_t)(k0 + bkr[ch]) * G3 + bcol + bn8[ch]]);
            }
        }

        // compute from smem[buf]
        const uint32_t asb = smB + (uint32_t)(buf * AS_BUF);
        const uint32_t bsb = smB + (uint32_t)(BS_BASE + buf * BS_BUF);
#pragma unroll
        for (int kh = 0; kh < 2; kh++) {
            uint32_t a[4][4];
#pragma unroll
            for (int tm = 0; tm < 4; tm++) {
                uint32_t addr = asb + aLaneOff +
                    (uint32_t)(((warp_m + tm * 16) * APAD + kh * 16) * 2);
                asm volatile(
                    "ldmatrix.sync.aligned.m8n8.x4.shared.b16 {%0,%1,%2,%3}, [%4];"
                    : "=r"(a[tm][0]), "=r"(a[tm][1]), "=r"(a[tm][2]), "=r"(a[tm][3])
                    : "r"(addr));
            }
            uint32_t b[4][2];
#pragma unroll
            for (int tnh = 0; tnh < 2; tnh++) {
                uint32_t addr = bsb + bLaneOff +
                    (uint32_t)((kh * 16 * BPAD + warp_n + tnh * 16) * 2);
                uint32_t r0, r1, r2, r3;
                asm volatile(
                    "ldmatrix.sync.aligned.m8n8.x4.trans.shared.b16 {%0,%1,%2,%3}, [%4];"
                    : "=r"(r0), "=r"(r1), "=r"(r2), "=r"(r3)
                    : "r"(addr));
                b[tnh * 2][0] = r0; b[tnh * 2][1] = r1;
                b[tnh * 2 + 1][0] = r2; b[tnh * 2 + 1][1] = r3;
            }
#pragma unroll
            for (int tm = 0; tm < 4; tm++)
#pragma unroll
                for (int tn = 0; tn < 4; tn++) {
                    asm volatile(
                        "mma.sync.aligned.m16n8k16.row.col.f32.bf16.bf16.f32 "
                        "{%0,%1,%2,%3}, {%4,%5,%6,%7}, {%8,%9}, {%0,%1,%2,%3};"
                        : "+f"(c[tm][tn][0]), "+f"(c[tm][tn][1]),
                          "+f"(c[tm][tn][2]), "+f"(c[tm][tn][3])
                        : "r"(a[tm][0]), "r"(a[tm][1]), "r"(a[tm][2]), "r"(a[tm][3]),
                          "r"(b[tn][0]), "r"(b[tn][1]));
                }
        }
    }

    // ---- smem-staged epilogue: 2 rounds of 64 rows, coalesced stores ----
    float* st = reinterpret_cast<float*>(smg);   // [64][EPAD]
#pragma unroll 1
    for (int rnd = 0; rnd < 2; rnd++) {
        __syncthreads();   // previous buffer use complete
        if ((wid >> 2) == rnd) {
            const int mb = lane >> 2;
            const int nb = (lane & 3) * 2;
#pragma unroll
            for (int tm = 0; tm < 4; tm++) {
                int ml = tm * 16 + mb;
#pragma unroll
                for (int tn = 0; tn < 4; tn++) {
                    int n0 = warp_n + tn * 8 + nb;
                    *reinterpret_cast<float2*>(&st[ml * EPAD + n0]) =
                        make_float2(c[tm][tn][0], c[tm][tn][1]);
                    *reinterpret_cast<float2*>(&st[(ml + 8) * EPAD + n0]) =
                        make_float2(c[tm][tn][2], c[tm][tn][3]);
                }
            }
        }
        __syncthreads();
        // all 256 threads: 64 rows x 32 float4, coalesced
        const int c4 = (tid & 31) * 4;
        float4 bv = *reinterpret_cast<const float4*>(&bias[bcol + c4]);
#pragma unroll
        for (int i = 0; i < 8; i++) {
            int row = i * 8 + (tid >> 5);
            float4 v = *reinterpret_cast<float4*>(&st[row * EPAD + c4]);
            v.x += bv.x; v.y += bv.y; v.z += bv.z; v.w += bv.w;
            *reinterpret_cast<float4*>(
                &g_gx[(size_t)(brow + rnd * 64 + row) * G3 + bcol + c4]) = v;
        }
    }
}

// ===========================================================================
// Kernel B: persistent GRU recurrence — EXACT R8/R12 configuration (1815us):
// bulk DSMEM h exchange, NKREG 20, TPB 256.
// ===========================================================================
#define TPB_B 256
#define NKREG 20
#define NKSM  12

#define ULL_W     0
#define ULL_H     (8 * NKSM * 3 * 32)          // 9216
#define ULL_RED   (ULL_H + 2 * 256 * 4)        // 11264
#define ULL_STAGE (ULL_RED + 8 * 4 * 3 * 32)   // 14336
#define ULL_TOT   (ULL_STAGE + 2 * 256)        // 14848
#define SMEM_B_BYTES (ULL_TOT * 8 + 16)

__device__ __forceinline__ float sigmoidf_fast(float x) {
    return __fdividef(1.0f, 1.0f + __expf(-x));
}
__device__ __forceinline__ float tanhf_fast(float x) {
    x = fminf(fmaxf(x, -15.f), 15.f);
    float e = __expf(2.f * x);
    return __fdividef(e - 1.f, e + 1.f);
}

__device__ __forceinline__ void mbar_wait_parity(uint32_t mbar, uint32_t parity) {
    asm volatile(
        "{\n\t"
        ".reg .pred P;\n\t"
        "WAIT_%=:\n\t"
        "mbarrier.try_wait.parity.acquire.cluster.shared::cta.b64 P, [%0], %1, 0x989680;\n\t"
        "@P bra DONE_%=;\n\t"
        "bra WAIT_%=;\n\t"
        "DONE_%=:\n\t"
        "}"
        :: "r"(mbar), "r"(parity) : "memory");
}

__global__ void __cluster_dims__(4, 1, 1) __launch_bounds__(TPB_B, 1)
gru_rec_kernel(const float* __restrict__ mask,
               const float* __restrict__ Whh,
               const float* __restrict__ bhh,
               float* __restrict__ out)
{
    extern __shared__ ull smu[];
    ull* Ws2   = smu + ULL_W;
    ull* hb2   = smu + ULL_H;
    ull* red   = smu + ULL_RED;
    ull* stage = smu + ULL_STAGE;

    const int tid = threadIdx.x;
    uint32_t rank;
    asm("mov.u32 %0, %%cluster_ctarank;" : "=r"(rank));
    const int ci = (int)blockIdx.x >> 2;

    uint32_t sm_u32;
    asm("{ .reg .u64 t; cvta.to.shared.u64 t, %1; cvt.u32.u64 %0, t; }"
        : "=r"(sm_u32) : "l"(smu));
    const uint32_t hb_u32    = sm_u32 + ULL_H * 8;
    const uint32_t stage_u32 = sm_u32 + ULL_STAGE * 8;
    const uint32_t mbar_u32  = sm_u32 + ULL_TOT * 8;

    if (tid == 0) {
        asm volatile("mbarrier.init.shared.b64 [%0], 1;" :: "r"(mbar_u32) : "memory");
        asm volatile("mbarrier.init.shared.b64 [%0], 1;" :: "r"(mbar_u32 + 8) : "memory");
        asm volatile("mbarrier.arrive.expect_tx.shared.b64 _, [%0], 8192;"
                     :: "r"(mbar_u32) : "memory");
        asm volatile("mbarrier.arrive.expect_tx.shared.b64 _, [%0], 8192;"
                     :: "r"(mbar_u32 + 8) : "memory");
    }

    for (int idx = tid; idx < 8 * NKSM * 3 * 32; idx += TPB_B) {
        int jp_ = idx & 31;
        int g   = (idx >> 5) % 3;
        int kk  = (idx / 96) % NKSM;
        int kq_ = idx / (96 * NKSM);
        int k   = kq_ * 32 + NKREG + kk;
        int base = k * G3 + g * 256 + (int)rank * 64 + jp_ * 2;
        Ws2[idx] = pk(Whh[base], Whh[base + 1]);
    }
    for (int idx = tid; idx < 2 * 256 * 4; idx += TPB_B) hb2[idx] = 0ull;

    const int kq = tid >> 5;
    const int jp = tid & 31;
    const int k0 = kq * 32;
    const int jg0 = (int)rank * 64 + jp * 2;

    ull wr[NKREG], wz[NKREG], wn[NKREG];
#pragma unroll
    for (int kk = 0; kk < NKREG; kk++) {
        int k = k0 + kk;
        wr[kk] = pk(Whh[k * G3 + jg0],       Whh[k * G3 + jg0 + 1]);
        wz[kk] = pk(Whh[k * G3 + 256 + jg0], Whh[k * G3 + 256 + jg0 + 1]);
        wn[kk] = pk(Whh[k * G3 + 512 + jg0], Whh[k * G3 + 512 + jg0 + 1]);
    }

    const int je = tid & 63;
    const int be = tid >> 6;
    const int jge = (int)rank * 64 + je;
    const float bhr = bhh[jge];
    const float bhz = bhh[256 + jge];
    const float bhn = bhh[512 + jge];
    const int bbg = ci * 4 + be;
    const float* gx_p = g_gx + (size_t)bbg * Ssz * G3;
    const float* m_p  = mask + (size_t)bbg * Ssz;
    float* out_p = out + (size_t)bbg * Ssz * Hsz + jge;

    __syncthreads();
    asm volatile("barrier.cluster.arrive.aligned;" ::: "memory");
    asm volatile("barrier.cluster.wait.aligned;" ::: "memory");

    int ph0 = 0, ph1 = 0;

    for (int t = 0; t < Ssz; t++) {
        const float* gxt = gx_p + (size_t)t * G3;
        float gxr = __ldcs(gxt + jge);
        float gxz = __ldcs(gxt + 256 + jge);
        float gxn = __ldcs(gxt + 512 + jge);
        float mt  = __ldg(m_p + t);

        const int mi = t & 1;
        if (t > 0) {
            uint32_t mb = mbar_u32 + (uint32_t)(mi * 8);
            if (mi == 0) { mbar_wait_parity(mb, ph0); ph0 ^= 1; }
            else         { mbar_wait_parity(mb, ph1); ph1 ^= 1; }
            if (tid == 0 && t + 2 < Ssz)
                asm volatile("mbarrier.arrive.expect_tx.shared.b64 _, [%0], 8192;"
                             :: "r"(mb) : "memory");
        }

        float hold = reinterpret_cast<const float*>(
            &hb2[mi * 1024 + jge * 4 + be])[0];

        ull ar[4] = {0, 0, 0, 0}, az[4] = {0, 0, 0, 0}, an[4] = {0, 0, 0, 0};
        const ull* hK = hb2 + mi * 1024 + k0 * 4;

#pragma unroll
        for (int kk = 0; kk < NKREG; kk++) {
            ulonglong2 h01 = *reinterpret_cast<const ulonglong2*>(hK + kk * 4);
            ulonglong2 h23 = *reinterpret_cast<const ulonglong2*>(hK + kk * 4 + 2);
            ull hh[4] = {h01.x, h01.y, h23.x, h23.y};
#pragma unroll
            for (int b = 0; b < 4; b++) {
                fma2(ar[b], hh[b], wr[kk]);
                fma2(az[b], hh[b], wz[kk]);
                fma2(an[b], hh[b], wn[kk]);
            }
        }
#pragma unroll
        for (int kk2 = 0; kk2 < NKSM; kk2++) {
            const ull* wb = Ws2 + ((kq * NKSM + kk2) * 3) * 32 + jp;
            ull w_r = wb[0];
            ull w_z = wb[32];
            ull w_n = wb[64];
            int kk = NKREG + kk2;
            ulonglong2 h01 = *reinterpret_cast<const ulonglong2*>(hK + kk * 4);
            ulonglong2 h23 = *reinterpret_cast<const ulonglong2*>(hK + kk * 4 + 2);
            ull hh[4] = {h01.x, h01.y, h23.x, h23.y};
#pragma unroll
            for (int b = 0; b < 4; b++) {
                fma2(ar[b], hh[b], w_r);
                fma2(az[b], hh[b], w_z);
                fma2(an[b], hh[b], w_n);
            }
        }

        {
            ull* rb = red + kq * 384 + jp;
#pragma unroll
            for (int b = 0; b < 4; b++) {
                rb[b * 96]      = ar[b];
                rb[b * 96 + 32] = az[b];
                rb[b * 96 + 64] = an[b];
            }
        }
        __syncthreads();

        {
            float ghr = bhr, ghz = bhz, ghn = bhn;
            const float* redf = reinterpret_cast<const float*>(red);
            const int fb = be * 192 + je;
#pragma unroll
            for (int q = 0; q < 8; q++) {
                const float* rp = redf + q * 768 + fb;
                ghr += rp[0];
                ghz += rp[64];
                ghn += rp[128];
            }
            float r = sigmoidf_fast(gxr + ghr);
            float z = sigmoidf_fast(gxz + ghz);
            float n = tanhf_fast(fmaf(r, ghn, gxn));
            float hnew = fmaf(z, hold - n, n);
            float hout = fmaf(mt, hnew - hold, hold);
            out_p[(size_t)t * Hsz] = hout;

            stage[(t & 1) * 256 + je * 4 + be] = pk(hout, hout);
        }
        __syncthreads();

        if (t < Ssz - 1 && tid < 4) {
            asm volatile("fence.proxy.async.shared::cta;" ::: "memory");
            uint32_t src = stage_u32 + (uint32_t)((t & 1) * 256 * 8);
            uint32_t dst_local = hb_u32 +
                (uint32_t)((((t + 1) & 1) * 1024 + (int)rank * 256) * 8);
            uint32_t mb_local = mbar_u32 + (uint32_t)(((t + 1) & 1) * 8);
            uint32_t dst_r, mb_r;
            asm volatile("mapa.shared::cluster.u32 %0, %1, %2;"
                         : "=r"(dst_r) : "r"(dst_local), "r"(tid));
            asm volatile("mapa.shared::cluster.u32 %0, %1, %2;"
                         : "=r"(mb_r) : "r"(mb_local), "r"(tid));
            asm volatile(
                "cp.async.bulk.shared::cluster.shared::cta."
                "mbarrier::complete_tx::bytes [%0], [%1], %2, [%3];"
                :: "r"(dst_r), "r"(src), "r"(2048), "r"(mb_r) : "memory");
        }
    }
}

// ---------------------------------------------------------------------------
extern "C" void kernel_launch(void* const* d_in, const int* in_sizes, int n_in,
                              void* d_out, int out_size)
{
    (void)in_sizes; (void)n_in; (void)out_size;
    const float* x    = (const float*)d_in[0];
    const float* mask = (const float*)d_in[1];
    const float* Wih  = (const float*)d_in[2];
    const float* Whh  = (const float*)d_in[3];
    const float* bih  = (const float*)d_in[4];
    const float* bhh  = (const float*)d_in[5];
    float* out = (float*)d_out;

    cudaFuncSetAttribute(gru_rec_kernel,
                         cudaFuncAttributeMaxDynamicSharedMemorySize,
                         SMEM_B_BYTES);

    // 1. split X and W_ih into bf16 hi/lo
    split_x_kernel<<<(Bsz * Ssz * Dsz) / (256 * 8), 256>>>(x);
    split_w_kernel<<<(Dsz * G3) / (256 * 8), 256>>>(Wih);

    // 2. gx GEMM on tensor cores (HMMA via mma.sync), staged epilogue
    dim3 gridA(G3 / 128, (Bsz * Ssz) / 128);   // 6 x 1024
    gemm_gx_mma<<<gridA, 256, SMEM_GEMM>>>(bih);

    // 3. recurrence
    gru_rec_kernel<<<Bsz, TPB_B, SMEM_B_BYTES>>>(mask, Whh, bhh, out);
}